// round 1
// baseline (speedup 1.0000x reference)
#include <cuda_runtime.h>

// Reference algebra collapses to out = x @ y:
//   x: [32, 48] fp32  (d_in[0], 1536 elems)
//   y: [48, 32] fp32  (d_in[1], 1536 elems)
//   out: [32, 32] fp32 (1024 elems)
// W0/W1/W2 are deterministic one-hot LT matrices whose composition with the
// roll-broadcasts and roll-reduction is exactly the matmul (no circular-wrap
// aliasing: max touched slot 49151 < 65536; the j-reduction covers the 64
// stride-1024 blocks exactly once). They are never read.

#define I_DIM 32
#define J_DIM 48
#define K_DIM 32

__global__ __launch_bounds__(1024, 1)
void einsum_matmul_kernel(const float* __restrict__ x,
                          const float* __restrict__ y,
                          float* __restrict__ out) {
    __shared__ float xs[I_DIM * J_DIM];   // 1536
    __shared__ float ys[J_DIM * K_DIM];   // 1536

    const int t = threadIdx.x;

    // 1024 threads load 1536 elements of each input (coalesced).
    if (t < I_DIM * J_DIM) xs[t] = x[t];
    if (t + 1024 < I_DIM * J_DIM) xs[t + 1024] = x[t + 1024];
    if (t < J_DIM * K_DIM) ys[t] = y[t];
    if (t + 1024 < J_DIM * K_DIM) ys[t + 1024] = y[t + 1024];
    __syncthreads();

    const int i = t >> 5;      // 0..31
    const int k = t & 31;      // 0..31

    float acc = 0.0f;
    #pragma unroll
    for (int j = 0; j < J_DIM; ++j) {
        // xs: warp-uniform broadcast; ys: stride-1 across lanes (conflict-free)
        acc = fmaf(xs[i * J_DIM + j], ys[j * K_DIM + k], acc);
    }
    out[t] = acc;
}

extern "C" void kernel_launch(void* const* d_in, const int* in_sizes, int n_in,
                              void* d_out, int out_size) {
    const float* x = (const float*)d_in[0];
    const float* y = (const float*)d_in[1];
    float* out = (float*)d_out;
    einsum_matmul_kernel<<<1, 1024>>>(x, y, out);
}

// round 2
// speedup vs baseline: 1.3416x; 1.3416x over previous
#include <cuda_runtime.h>

// out = x @ y  (see R1 derivation: the W0/W1/W2 one-hot LT + roll pipeline is
// exactly a 32x48 @ 48x32 fp32 matmul; W* are never read).
//
// R2: latency-optimized. 32 CTAs x 32 threads, one output row per CTA, one
// output element per thread. No shared memory, no __syncthreads. Fully
// unrolled j-loop so ptxas front-batches the 48 coalesced y-loads (MLP ~48
// hides the single DRAM round trip). x loads are warp-uniform. 4-way split
// accumulators shorten the dependent-FMA tail.

#define I_DIM 32
#define J_DIM 48
#define K_DIM 32

__global__ __launch_bounds__(32, 1)
void einsum_matmul_kernel(const float* __restrict__ x,
                          const float* __restrict__ y,
                          float* __restrict__ out) {
    const int i = blockIdx.x;      // 0..31  output row
    const int k = threadIdx.x;     // 0..31  output col

    const float* __restrict__ xr = x + i * J_DIM;

    float a0 = 0.0f, a1 = 0.0f, a2 = 0.0f, a3 = 0.0f;

    #pragma unroll
    for (int j = 0; j < J_DIM; j += 4) {
        // Coalesced 128B loads of y rows; warp-uniform x loads.
        float y0 = __ldg(&y[(j + 0) * K_DIM + k]);
        float y1 = __ldg(&y[(j + 1) * K_DIM + k]);
        float y2 = __ldg(&y[(j + 2) * K_DIM + k]);
        float y3 = __ldg(&y[(j + 3) * K_DIM + k]);
        float x0 = __ldg(&xr[j + 0]);
        float x1 = __ldg(&xr[j + 1]);
        float x2 = __ldg(&xr[j + 2]);
        float x3 = __ldg(&xr[j + 3]);
        a0 = fmaf(x0, y0, a0);
        a1 = fmaf(x1, y1, a1);
        a2 = fmaf(x2, y2, a2);
        a3 = fmaf(x3, y3, a3);
    }

    out[i * K_DIM + k] = (a0 + a1) + (a2 + a3);
}

extern "C" void kernel_launch(void* const* d_in, const int* in_sizes, int n_in,
                              void* d_out, int out_size) {
    const float* x = (const float*)d_in[0];
    const float* y = (const float*)d_in[1];
    float* out = (float*)d_out;
    einsum_matmul_kernel<<<I_DIM, K_DIM>>>(x, y, out);
}

// round 3
// speedup vs baseline: 1.3585x; 1.0126x over previous
#include <cuda_runtime.h>

// out = x @ y  (32x48 @ 48x32 fp32). The W0/W1/W2 one-hot LT matrices plus the
// roll-broadcast / roll-reduce pipeline in the reference compose to exactly
// this matmul (no circular-wrap aliasing); they are never read.
//
// R3: minimize per-warp critical path. 128 CTAs x 32 threads.
//   blockIdx.x = b: i = b >> 2 (output row), kg = b & 3 (group of 8 k's).
//   lane = k_local*4 + jseg: k = kg*8 + k_local, lane sums j in [jseg*12, +12).
//   Per thread: 3 float4 x-loads + 12 y-loads + 12 FMA, then 2 shfl_xor
//   butterfly over the 4 jseg lanes; jseg==0 lane stores.
// No smem, no barriers; critical path ~= launch + 1 mem round trip + ~110 cyc.

#define I_DIM 32
#define J_DIM 48
#define K_DIM 32

__global__ __launch_bounds__(32, 1)
void einsum_matmul_kernel(const float* __restrict__ x,
                          const float* __restrict__ y,
                          float* __restrict__ out) {
    const int b = blockIdx.x;          // 0..127
    const int i = b >> 2;              // output row 0..31
    const int kg = b & 3;              // k-group 0..3

    const int lane = threadIdx.x;      // 0..31
    const int k_local = lane >> 2;     // 0..7
    const int jseg = lane & 3;         // 0..3
    const int k = kg * 8 + k_local;    // 0..31
    const int j0 = jseg * 12;          // j base for this lane

    // x row slice: 12 floats, 16B-aligned (i*48 and jseg*12 both mult of 4).
    const float4* __restrict__ x4 =
        (const float4*)(x + i * J_DIM + j0);
    float4 xa = __ldg(&x4[0]);
    float4 xb = __ldg(&x4[1]);
    float4 xc = __ldg(&x4[2]);

    const float* __restrict__ yp = y + j0 * K_DIM + k;

    // 12 independent y loads (front-batched), 12 FMAs, 3 accumulators.
    float a0 = 0.0f, a1 = 0.0f, a2 = 0.0f;
    float y0  = __ldg(&yp[0 * K_DIM]);
    float y1  = __ldg(&yp[1 * K_DIM]);
    float y2  = __ldg(&yp[2 * K_DIM]);
    float y3  = __ldg(&yp[3 * K_DIM]);
    float y4  = __ldg(&yp[4 * K_DIM]);
    float y5  = __ldg(&yp[5 * K_DIM]);
    float y6  = __ldg(&yp[6 * K_DIM]);
    float y7  = __ldg(&yp[7 * K_DIM]);
    float y8  = __ldg(&yp[8 * K_DIM]);
    float y9  = __ldg(&yp[9 * K_DIM]);
    float y10 = __ldg(&yp[10 * K_DIM]);
    float y11 = __ldg(&yp[11 * K_DIM]);

    a0 = fmaf(xa.x, y0, a0);
    a1 = fmaf(xa.y, y1, a1);
    a2 = fmaf(xa.z, y2, a2);
    a0 = fmaf(xa.w, y3, a0);
    a1 = fmaf(xb.x, y4, a1);
    a2 = fmaf(xb.y, y5, a2);
    a0 = fmaf(xb.z, y6, a0);
    a1 = fmaf(xb.w, y7, a1);
    a2 = fmaf(xc.x, y8, a2);
    a0 = fmaf(xc.y, y9, a0);
    a1 = fmaf(xc.z, y10, a1);
    a2 = fmaf(xc.w, y11, a2);

    float acc = (a0 + a1) + a2;

    // Butterfly reduce over the 4 jseg lanes (consecutive lanes).
    acc += __shfl_xor_sync(0xFFFFFFFFu, acc, 1);
    acc += __shfl_xor_sync(0xFFFFFFFFu, acc, 2);

    if (jseg == 0) {
        out[i * K_DIM + k] = acc;
    }
}

extern "C" void kernel_launch(void* const* d_in, const int* in_sizes, int n_in,
                              void* d_out, int out_size) {
    const float* x = (const float*)d_in[0];
    const float* y = (const float*)d_in[1];
    float* out = (float*)d_out;
    einsum_matmul_kernel<<<128, 32>>>(x, y, out);
}